// round 11
// baseline (speedup 1.0000x reference)
#include <cuda_runtime.h>
#include <cuda_bf16.h>
#include <mma.h>
#include <math.h>
#include <cstdint>

using namespace nvcuda;

// ---------------- problem constants ----------------
static constexpr int BB    = 4;
static constexpr int HH    = 192;
static constexpr int WW    = 192;
static constexpr int DIM   = 256;
static constexpr int HEADS = 8;
static constexpr int HD    = 32;
static constexpr int WIN   = 8;
static constexpr int SHIFT = 4;
static constexpr int HID   = 1024;

static constexpr int L     = HH * WW;          // 36864
static constexpr int MROWS = BB * L;           // 147456
static constexpr int NWB   = HH / WIN;         // 24
static constexpr int NWIN  = BB * NWB * NWB;   // 2304
static constexpr float SCALE = 0.17677669529663687f; // 1/sqrt(32)

// ---------------- scratch ----------------
// h2: LN1 out, 2-component [M][2K]=[hi|lo] (QKV uses A-split).
// attn1/ln21/hid1: single bf16 (their GEMMs use B-split instead: A_hi*(B_hi+B_lo)).
__device__ __nv_bfloat16 g_h2   [(size_t)MROWS * 2 * DIM];
__device__ float         g_qkv  [(size_t)MROWS * 3 * DIM];   // fp32 (attention reads tf32)
__device__ __nv_bfloat16 g_attn1[(size_t)MROWS * DIM];
__device__ float         g_x2   [(size_t)MROWS * DIM];
__device__ __nv_bfloat16 g_ln21 [(size_t)MROWS * DIM];
__device__ __nv_bfloat16 g_hid1 [(size_t)MROWS * HID];

__device__ __nv_bfloat16 g_wqkv2 [2 * DIM * 3 * DIM];
__device__ __nv_bfloat16 g_wproj2[2 * DIM * DIM];
__device__ __nv_bfloat16 g_wfc12 [2 * DIM * HID];
__device__ __nv_bfloat16 g_wfc22 [2 * HID * DIM];

__device__ __forceinline__ void split2(float v, __nv_bfloat16& hi, __nv_bfloat16& lo) {
    hi = __float2bfloat16(v);
    lo = __float2bfloat16(v - __bfloat162float(hi));
}

__device__ __forceinline__ int win_row_to_token(int r) {
    int widx = r >> 6;
    int t    = r & 63;
    int b    = widx / (NWB * NWB);
    int wrem = widx - b * (NWB * NWB);
    int wh   = wrem / NWB;
    int ww   = wrem - wh * NWB;
    int ty   = t >> 3, tx = t & 7;
    int hp   = wh * WIN + ty + SHIFT; if (hp >= HH) hp -= HH;
    int wp   = ww * WIN + tx + SHIFT; if (wp >= WW) wp -= WW;
    return b * L + hp * WW + wp;
}

// ---------------- all-weights fp32 [K][N] -> split bf16 [2K][N], one launch ----------------
__global__ void cvt_all(const float* __restrict__ qkv_w, const float* __restrict__ proj_w,
                        const float* __restrict__ fc1_w, const float* __restrict__ fc2_w,
                        __nv_bfloat16* __restrict__ wq, __nv_bfloat16* __restrict__ wp,
                        __nv_bfloat16* __restrict__ w1, __nv_bfloat16* __restrict__ w2) {
    int i = blockIdx.x * blockDim.x + threadIdx.x;
    const float* src; __nv_bfloat16* dst; int KN;
    int j = i;
    if (j < 196608)                     { src = qkv_w;  dst = wq; KN = 196608; }
    else if ((j -= 196608) < 65536)     { src = proj_w; dst = wp; KN = 65536; }
    else if ((j -= 65536)  < 262144)    { src = fc1_w;  dst = w1; KN = 262144; }
    else if ((j -= 262144) < 262144)    { src = fc2_w;  dst = w2; KN = 262144; }
    else return;
    __nv_bfloat16 hi, lo;
    split2(src[j], hi, lo);
    dst[j]      = hi;
    dst[KN + j] = lo;
}

// ---------------- LayerNorm fp32 -> split bf16 [M][2K] (LN1) ----------------
__global__ void ln_split_kernel(const float* __restrict__ x, const float* __restrict__ g,
                                const float* __restrict__ b, __nv_bfloat16* __restrict__ out) {
    int gw   = (blockIdx.x * blockDim.x + threadIdx.x) >> 5;
    int lane = threadIdx.x & 31;
    const float4* rp = (const float4*)(x + (size_t)gw * DIM);
    float4 a0 = rp[lane * 2], a1 = rp[lane * 2 + 1];
    float s  = a0.x + a0.y + a0.z + a0.w + a1.x + a1.y + a1.z + a1.w;
    float sq = a0.x*a0.x + a0.y*a0.y + a0.z*a0.z + a0.w*a0.w
             + a1.x*a1.x + a1.y*a1.y + a1.z*a1.z + a1.w*a1.w;
    #pragma unroll
    for (int o = 16; o; o >>= 1) {
        s  += __shfl_xor_sync(0xffffffffu, s,  o);
        sq += __shfl_xor_sync(0xffffffffu, sq, o);
    }
    float mean = s * (1.0f / DIM);
    float var  = sq * (1.0f / DIM) - mean * mean;
    float rstd = rsqrtf(var + 1e-5f);
    const float4* gp = (const float4*)g;
    const float4* bp = (const float4*)b;
    float4 g0 = gp[lane*2], g1 = gp[lane*2+1], b0 = bp[lane*2], b1 = bp[lane*2+1];
    float y[8];
    y[0] = (a0.x - mean) * rstd * g0.x + b0.x;
    y[1] = (a0.y - mean) * rstd * g0.y + b0.y;
    y[2] = (a0.z - mean) * rstd * g0.z + b0.z;
    y[3] = (a0.w - mean) * rstd * g0.w + b0.w;
    y[4] = (a1.x - mean) * rstd * g1.x + b1.x;
    y[5] = (a1.y - mean) * rstd * g1.y + b1.y;
    y[6] = (a1.z - mean) * rstd * g1.z + b1.z;
    y[7] = (a1.w - mean) * rstd * g1.w + b1.w;
    __nv_bfloat16 hi[8], lo[8];
    #pragma unroll
    for (int i = 0; i < 8; i++) split2(y[i], hi[i], lo[i]);
    __nv_bfloat16* base = out + (size_t)gw * (2 * DIM) + lane * 8;
    *(uint4*)(base)       = *(uint4*)hi;
    *(uint4*)(base + DIM) = *(uint4*)lo;
}

// ---------------- LayerNorm fp32 -> single bf16 [M][K] (LN2; fc1 uses B-split) ----------------
__global__ void ln_single_kernel(const float* __restrict__ x, const float* __restrict__ g,
                                 const float* __restrict__ b, __nv_bfloat16* __restrict__ out) {
    int gw   = (blockIdx.x * blockDim.x + threadIdx.x) >> 5;
    int lane = threadIdx.x & 31;
    const float4* rp = (const float4*)(x + (size_t)gw * DIM);
    float4 a0 = rp[lane * 2], a1 = rp[lane * 2 + 1];
    float s  = a0.x + a0.y + a0.z + a0.w + a1.x + a1.y + a1.z + a1.w;
    float sq = a0.x*a0.x + a0.y*a0.y + a0.z*a0.z + a0.w*a0.w
             + a1.x*a1.x + a1.y*a1.y + a1.z*a1.z + a1.w*a1.w;
    #pragma unroll
    for (int o = 16; o; o >>= 1) {
        s  += __shfl_xor_sync(0xffffffffu, s,  o);
        sq += __shfl_xor_sync(0xffffffffu, sq, o);
    }
    float mean = s * (1.0f / DIM);
    float var  = sq * (1.0f / DIM) - mean * mean;
    float rstd = rsqrtf(var + 1e-5f);
    const float4* gp = (const float4*)g;
    const float4* bp = (const float4*)b;
    float4 g0 = gp[lane*2], g1 = gp[lane*2+1], b0 = bp[lane*2], b1 = bp[lane*2+1];
    __nv_bfloat16 h[8];
    h[0] = __float2bfloat16((a0.x - mean) * rstd * g0.x + b0.x);
    h[1] = __float2bfloat16((a0.y - mean) * rstd * g0.y + b0.y);
    h[2] = __float2bfloat16((a0.z - mean) * rstd * g0.z + b0.z);
    h[3] = __float2bfloat16((a0.w - mean) * rstd * g0.w + b0.w);
    h[4] = __float2bfloat16((a1.x - mean) * rstd * g1.x + b1.x);
    h[5] = __float2bfloat16((a1.y - mean) * rstd * g1.y + b1.y);
    h[6] = __float2bfloat16((a1.z - mean) * rstd * g1.z + b1.z);
    h[7] = __float2bfloat16((a1.w - mean) * rstd * g1.w + b1.w);
    *(uint4*)(out + (size_t)gw * DIM + lane * 8) = *(uint4*)h;
}

// ---------------- GEMM: bf16 wmma, 64x64 warp tiles, 3-stage pipeline ----------------
// A2: A stored [M][2K]=[hi|lo], both used (al*BH term). A2=0: A is [M][K] single.
// B2: also use B_lo rows (ah*BL term).
// QKV-qk: A2=1,B2=1 (3 terms). QKV-v: A2=1,B2=0. proj/fc1/fc2: A2=0,B2=1.
static constexpr int Bb_M = 128, Bb_N = 128, Bb_K = 32, STAGES = 3;
static constexpr int NTHREADS = 128;
static constexpr int LDA = Bb_K + 8;     // 40
static constexpr int LDB = Bb_N + 8;     // 136
static constexpr int AH_ST = Bb_M * LDA; // 5120
static constexpr int BH_ST = Bb_K * LDB; // 4352
static constexpr int STAGE_E = 2 * AH_ST + 2 * BH_ST;   // 18944 elems
static constexpr int LDC_S = 132;
static constexpr int SMEM_GEMM = STAGES * STAGE_E * 2;  // 113664 B

static constexpr int EPI_QKV = 0, EPI_PROJ = 1, EPI_FC1 = 2, EPI_FC2 = 3;

__device__ __forceinline__ void cpa16(void* sptr, const void* gptr) {
    unsigned int s = (unsigned int)__cvta_generic_to_shared(sptr);
    asm volatile("cp.async.cg.shared.global [%0], [%1], 16;\n" :: "r"(s), "l"(gptr));
}

template<int EPI, int A2, int B2>
__global__ void __launch_bounds__(NTHREADS, 2)
gemm2(const __nv_bfloat16* __restrict__ A,      // [M][A2?2K:K]
      const __nv_bfloat16* __restrict__ Bm,     // [2K][N]
      const float* __restrict__ bias,
      const float* __restrict__ res,
      float* __restrict__ outF,
      __nv_bfloat16* __restrict__ outH,
      int N, int K, int nOff) {
    extern __shared__ char smem[];
    __nv_bfloat16* sm = (__nv_bfloat16*)smem;
    float*         Cs = (float*)smem;

    int tid  = threadIdx.x;
    int warp = tid >> 5;
    int wm   = warp >> 1;
    int wn   = warp & 1;
    int bn   = nOff + blockIdx.x * Bb_N;
    int bm   = blockIdx.y * Bb_M;
    int KA   = A2 ? 2 * K : K;        // A row stride
    int T    = K / Bb_K;

    wmma::fragment<wmma::accumulator, 16, 16, 16, float> acc[4][4];
    #pragma unroll
    for (int i = 0; i < 4; i++)
        #pragma unroll
        for (int j = 0; j < 4; j++)
            wmma::fill_fragment(acc[i][j], 0.0f);

    auto loads = [&](int t) {
        int k0 = t * Bb_K;
        int st = t % STAGES;
        __nv_bfloat16* AH = sm + st * STAGE_E;
        __nv_bfloat16* AL = AH + AH_ST;
        __nv_bfloat16* BH = AL + AH_ST;
        __nv_bfloat16* BL = BH + BH_ST;
        #pragma unroll
        for (int i = 0; i < 4; i++) {
            int c = tid + i * NTHREADS;
            int r = c >> 2, cc = (c & 3) * 8;
            const __nv_bfloat16* src = A + (size_t)(bm + r) * KA + k0 + cc;
            cpa16(&AH[r * LDA + cc], src);
            if (A2) cpa16(&AL[r * LDA + cc], src + K);
        }
        #pragma unroll
        for (int i = 0; i < 4; i++) {
            int c = tid + i * NTHREADS;
            int r = c >> 4, cc = (c & 15) * 8;
            cpa16(&BH[r * LDB + cc], Bm + (size_t)(k0 + r) * N + bn + cc);
            if (B2)
                cpa16(&BL[r * LDB + cc], Bm + (size_t)(K + k0 + r) * N + bn + cc);
        }
        asm volatile("cp.async.commit_group;\n" ::);
    };

    loads(0);
    loads(1);

    for (int t = 0; t < T; t++) {
        asm volatile("cp.async.wait_group 1;\n" ::);
        __syncthreads();
        if (t + 2 < T) loads(t + 2);

        int st = t % STAGES;
        const __nv_bfloat16* AH = sm + st * STAGE_E;
        const __nv_bfloat16* AL = AH + AH_ST;
        const __nv_bfloat16* BH = AL + AH_ST;
        const __nv_bfloat16* BL = BH + BH_ST;

        #pragma unroll
        for (int kk = 0; kk < Bb_K; kk += 16) {
            wmma::fragment<wmma::matrix_a, 16, 16, 16, __nv_bfloat16, wmma::row_major> ah[4], al[4];
            wmma::fragment<wmma::matrix_b, 16, 16, 16, __nv_bfloat16, wmma::row_major> bf[4];
            #pragma unroll
            for (int i = 0; i < 4; i++) {
                wmma::load_matrix_sync(ah[i], &AH[(wm * 64 + i * 16) * LDA + kk], LDA);
                if (A2)
                    wmma::load_matrix_sync(al[i], &AL[(wm * 64 + i * 16) * LDA + kk], LDA);
            }
            #pragma unroll
            for (int j = 0; j < 4; j++)
                wmma::load_matrix_sync(bf[j], &BH[kk * LDB + wn * 64 + j * 16], LDB);
            #pragma unroll
            for (int i = 0; i < 4; i++)
                #pragma unroll
                for (int j = 0; j < 4; j++) {
                    wmma::mma_sync(acc[i][j], ah[i], bf[j], acc[i][j]);
                    if (A2) wmma::mma_sync(acc[i][j], al[i], bf[j], acc[i][j]);
                }
            if (B2) {
                #pragma unroll
                for (int j = 0; j < 4; j++)
                    wmma::load_matrix_sync(bf[j], &BL[kk * LDB + wn * 64 + j * 16], LDB);
                #pragma unroll
                for (int i = 0; i < 4; i++)
                    #pragma unroll
                    for (int j = 0; j < 4; j++)
                        wmma::mma_sync(acc[i][j], ah[i], bf[j], acc[i][j]);
            }
        }
    }

    asm volatile("cp.async.wait_all;\n" ::);
    __syncthreads();

    #pragma unroll
    for (int i = 0; i < 4; i++)
        #pragma unroll
        for (int j = 0; j < 4; j++)
            wmma::store_matrix_sync(&Cs[(wm * 64 + i * 16) * LDC_S + wn * 64 + j * 16],
                                    acc[i][j], LDC_S, wmma::mem_row_major);
    __syncthreads();

    #pragma unroll 4
    for (int e = 0; e < 32; e++) {
        int idx = tid + e * NTHREADS;
        int r = idx >> 5;
        int c = (idx & 31) * 4;
        float4 v = *(float4*)&Cs[r * LDC_S + c];
        int gr = bm + r, gc = bn + c;
        float4 bv = *(const float4*)(bias + gc);
        if (EPI == EPI_QKV) {
            float4 o = {v.x + bv.x, v.y + bv.y, v.z + bv.z, v.w + bv.w};
            *(float4*)(outF + (size_t)gr * N + gc) = o;
        } else if (EPI == EPI_PROJ) {
            int tok = win_row_to_token(gr);
            size_t off = (size_t)tok * DIM + gc;
            float4 rv = *(const float4*)(res + off);
            float4 o = {v.x + bv.x + rv.x, v.y + bv.y + rv.y,
                        v.z + bv.z + rv.z, v.w + bv.w + rv.w};
            *(float4*)(outF + off) = o;
        } else if (EPI == EPI_FC1) {
            float tv[4] = {v.x + bv.x, v.y + bv.y, v.z + bv.z, v.w + bv.w};
            __nv_bfloat16 h[4];
            #pragma unroll
            for (int q = 0; q < 4; q++)
                h[q] = __float2bfloat16(0.5f * tv[q] * (1.0f + erff(tv[q] * 0.70710678118654752f)));
            *(uint2*)(outH + (size_t)gr * HID + gc) = *(uint2*)h;
        } else { // EPI_FC2
            size_t off = (size_t)gr * N + gc;
            float4 rv = *(const float4*)(res + off);
            float4 o = {v.x + bv.x + rv.x, v.y + bv.y + rv.y,
                        v.z + bv.z + rv.z, v.w + bv.w + rv.w};
            *(float4*)(outF + off) = o;
        }
    }
}

// ---------------- attention: tf32 wmma, one block per (window, head), 128 threads ----------------
// smem 45200 B -> 5 CTAs/SM. In-place softmax + warp-local PV (as R8); S LD = 64 floats.
static constexpr int AQ_LD = 36;
static constexpr int AS_LD = 64;
static constexpr int OFF_Q = 0;
static constexpr int OFF_K = OFF_Q + 64 * AQ_LD;     // 2304
static constexpr int OFF_V = OFF_K + 64 * AQ_LD;     // 4608
static constexpr int OFF_S = OFF_V + 64 * AQ_LD;     // 6912
static constexpr int OFF_B = OFF_S + 64 * AS_LD;     // 11008
static constexpr int OFF_T = OFF_B + 228;            // 11236
static constexpr int ATT_SMEM = (OFF_T + 64) * 4;    // 45200 B

template<class Frag>
__device__ __forceinline__ void to_tf32(Frag& f) {
    #pragma unroll
    for (int t = 0; t < f.num_elements; t++) f.x[t] = wmma::__float_to_tf32(f.x[t]);
}

__global__ void attn_kernel(const float* __restrict__ qkv,
                            const float* __restrict__ table,
                            __nv_bfloat16* __restrict__ out1) {
    extern __shared__ float sm[];
    float* sQ = sm + OFF_Q;
    float* sK = sm + OFF_K;
    float* sV = sm + OFF_V;
    float* sS = sm + OFF_S;
    float* sB = sm + OFF_B;
    int*   sTok = (int*)(sm + OFF_T);

    int widx = blockIdx.x, head = blockIdx.y;
    int tid = threadIdx.x, lane = tid & 31, w = tid >> 5;

    if (tid < 225) sB[tid] = table[tid * HEADS + head];
    if (tid < 64)  sTok[tid] = win_row_to_token(widx * 64 + tid);
    __syncthreads();

    #pragma unroll
    for (int i = 0; i < 4; i++) {
        int c = tid + i * 128;
        int r = c >> 3, cc = (c & 7) * 4;
        size_t base = (size_t)sTok[r] * (3 * DIM) + head * HD + cc;
        *(float4*)&sQ[r * AQ_LD + cc] = *(const float4*)&qkv[base];
        *(float4*)&sK[r * AQ_LD + cc] = *(const float4*)&qkv[base + DIM];
        *(float4*)&sV[r * AQ_LD + cc] = *(const float4*)&qkv[base + 2 * DIM];
    }
    __syncthreads();

    // S = Q @ K^T  (warp w -> rows [w*16, w*16+16))
    {
        wmma::fragment<wmma::accumulator, 16, 16, 8, float> acc[4];
        #pragma unroll
        for (int j = 0; j < 4; j++) wmma::fill_fragment(acc[j], 0.0f);
        #pragma unroll
        for (int kk = 0; kk < 32; kk += 8) {
            wmma::fragment<wmma::matrix_a, 16, 16, 8, wmma::precision::tf32, wmma::row_major> af;
            wmma::load_matrix_sync(af, &sQ[(w * 16) * AQ_LD + kk], AQ_LD);
            to_tf32(af);
            #pragma unroll
            for (int j = 0; j < 4; j++) {
                wmma::fragment<wmma::matrix_b, 16, 16, 8, wmma::precision::tf32, wmma::col_major> bf;
                wmma::load_matrix_sync(bf, &sK[(j * 16) * AQ_LD + kk], AQ_LD);
                to_tf32(bf);
                wmma::mma_sync(acc[j], af, bf, acc[j]);
            }
        }
        #pragma unroll
        for (int j = 0; j < 4; j++)
            wmma::store_matrix_sync(&sS[(w * 16) * AS_LD + j * 16], acc[j], AS_LD, wmma::mem_row_major);
    }

    // softmax in place (warp-local rows)
    #pragma unroll 2
    for (int rr = 0; rr < 16; rr++) {
        int r = w * 16 + rr;
        int yi = r >> 3, xi = r & 7;
        int c0 = lane, c1 = lane + 32;
        int i0 = (yi - (c0 >> 3) + 7) * 15 + (xi - (c0 & 7) + 7);
        int i1 = (yi - (c1 >> 3) + 7) * 15 + (xi - (c1 & 7) + 7);
        float v0 = sS[r * AS_LD + c0] * SCALE + sB[i0];
        float v1 = sS[r * AS_LD + c1] * SCALE + sB[i1];
        float m = fmaxf(v0, v1);
        #pragma unroll
        for (int o = 16; o; o >>= 1) m = fmaxf(m, __shfl_xor_sync(0xffffffffu, m, o));
        float e0 = __expf(v0 - m), e1 = __expf(v1 - m);
        float s = e0 + e1;
        #pragma unroll
        for (int o = 16; o; o >>= 1) s += __shfl_xor_sync(0xffffffffu, s, o);
        float inv = 1.0f / s;
        sS[r * AS_LD + c0] = e0 * inv;
        sS[r * AS_LD + c1] = e1 * inv;
    }
    __syncwarp();

    // O = P @ V (warp-local rows)
    {
        wmma::fragment<wmma::accumulator, 16, 16, 8, float> acc[2];
        #pragma unroll
        for (int j = 0; j < 2; j++) wmma::fill_fragment(acc[j], 0.0f);
        #pragma unroll
        for (int k0 = 0; k0 < 64; k0 += 8) {
            wmma::fragment<wmma::matrix_a, 16, 16, 8, wmma::precision::tf32, wmma::row_major> af;
            wmma::load_matrix_sync(af, &sS[(w * 16) * AS_LD + k0], AS_LD);
            to_tf32(af);
            #pragma unroll
            for (int j = 0; j < 2; j++) {
                wmma::fragment<wmma::matrix_b, 16, 16, 8, wmma::precision::tf32, wmma::row_major> bf;
                wmma::load_matrix_sync(bf, &sV[k0 * AQ_LD + j * 16], AQ_LD);
                to_tf32(bf);
                wmma::mma_sync(acc[j], af, bf, acc[j]);
            }
        }
        #pragma unroll
        for (int j = 0; j < 2; j++)
            wmma::store_matrix_sync(&sS[(w * 16) * AS_LD + j * 16], acc[j], AS_LD, wmma::mem_row_major);
    }
    __syncthreads();

    // write O (windowed order), single bf16 (proj uses B-split)
    #pragma unroll
    for (int i = 0; i < 16; i++) {
        int idx = tid + i * 128;
        int r = idx >> 5, c = idx & 31;
        out1[((size_t)widx * 64 + r) * DIM + head * HD + c] =
            __float2bfloat16(sS[r * AS_LD + c]);
    }
}

// ---------------- launch ----------------
extern "C" void kernel_launch(void* const* d_in, const int* in_sizes, int n_in,
                              void* d_out, int out_size) {
    const float* x        = (const float*)d_in[0];
    const float* norm1_g  = (const float*)d_in[1];
    const float* norm1_b  = (const float*)d_in[2];
    const float* qkv_w    = (const float*)d_in[3];
    const float* qkv_b    = (const float*)d_in[4];
    const float* bias_tab = (const float*)d_in[5];
    const float* proj_w   = (const float*)d_in[6];
    const float* proj_b   = (const float*)d_in[7];
    const float* norm2_g  = (const float*)d_in[8];
    const float* norm2_b  = (const float*)d_in[9];
    const float* fc1_w    = (const float*)d_in[10];
    const float* fc1_b    = (const float*)d_in[11];
    const float* fc2_w    = (const float*)d_in[12];
    const float* fc2_b    = (const float*)d_in[13];
    float* out            = (float*)d_out;

    void *p;
    cudaGetSymbolAddress(&p, g_h2);    __nv_bfloat16* ph2   = (__nv_bfloat16*)p;
    cudaGetSymbolAddress(&p, g_qkv);   float*         pqkv  = (float*)p;
    cudaGetSymbolAddress(&p, g_attn1); __nv_bfloat16* pat1  = (__nv_bfloat16*)p;
    cudaGetSymbolAddress(&p, g_x2);    float*         px2   = (float*)p;
    cudaGetSymbolAddress(&p, g_ln21);  __nv_bfloat16* pln21 = (__nv_bfloat16*)p;
    cudaGetSymbolAddress(&p, g_hid1);  __nv_bfloat16* phid1 = (__nv_bfloat16*)p;
    cudaGetSymbolAddress(&p, g_wqkv2); __nv_bfloat16* pwq2  = (__nv_bfloat16*)p;
    cudaGetSymbolAddress(&p, g_wproj2);__nv_bfloat16* pwp2  = (__nv_bfloat16*)p;
    cudaGetSymbolAddress(&p, g_wfc12); __nv_bfloat16* pw12  = (__nv_bfloat16*)p;
    cudaGetSymbolAddress(&p, g_wfc22); __nv_bfloat16* pw22  = (__nv_bfloat16*)p;

    cudaFuncSetAttribute((const void*)gemm2<EPI_QKV, 1, 1>,  cudaFuncAttributeMaxDynamicSharedMemorySize, SMEM_GEMM);
    cudaFuncSetAttribute((const void*)gemm2<EPI_QKV, 1, 0>,  cudaFuncAttributeMaxDynamicSharedMemorySize, SMEM_GEMM);
    cudaFuncSetAttribute((const void*)gemm2<EPI_PROJ, 0, 1>, cudaFuncAttributeMaxDynamicSharedMemorySize, SMEM_GEMM);
    cudaFuncSetAttribute((const void*)gemm2<EPI_FC1, 0, 1>,  cudaFuncAttributeMaxDynamicSharedMemorySize, SMEM_GEMM);
    cudaFuncSetAttribute((const void*)gemm2<EPI_FC2, 0, 1>,  cudaFuncAttributeMaxDynamicSharedMemorySize, SMEM_GEMM);
    cudaFuncSetAttribute(attn_kernel, cudaFuncAttributeMaxDynamicSharedMemorySize, ATT_SMEM);

    const int MT = MROWS / Bb_M;   // 1152

    // 0. split weights
    cvt_all<<<(786432 + 255)/256, 256>>>(qkv_w, proj_w, fc1_w, fc2_w, pwq2, pwp2, pw12, pw22);

    // 1. LN1 -> h2 (2-component)
    ln_split_kernel<<<MROWS/8, 256>>>(x, norm1_g, norm1_b, ph2);

    // 2a. QKV q,k columns (N cols [0,512), 3-term) -> qkv f32
    gemm2<EPI_QKV, 1, 1><<<dim3(4, MT), NTHREADS, SMEM_GEMM>>>(
        ph2, pwq2, qkv_b, nullptr, pqkv, nullptr, 3*DIM, DIM, 0);
    // 2b. QKV v columns (N cols [512,768), 2-term A-split)
    gemm2<EPI_QKV, 1, 0><<<dim3(2, MT), NTHREADS, SMEM_GEMM>>>(
        ph2, pwq2, qkv_b, nullptr, pqkv, nullptr, 3*DIM, DIM, 512);

    // 3. windowed attention (tf32) -> attn1 (single bf16, windowed order)
    attn_kernel<<<dim3(NWIN, HEADS), 128, ATT_SMEM>>>(pqkv, bias_tab, pat1);

    // 4. proj (A single, B split) + shortcut scatter -> x2
    gemm2<EPI_PROJ, 0, 1><<<dim3(2, MT), NTHREADS, SMEM_GEMM>>>(
        pat1, pwp2, proj_b, x, px2, nullptr, DIM, DIM, 0);

    // 5. LN2 -> ln21 (single)
    ln_single_kernel<<<MROWS/8, 256>>>(px2, norm2_g, norm2_b, pln21);

    // 6. fc1 (A single, B split) + GELU -> hid1 (single)
    gemm2<EPI_FC1, 0, 1><<<dim3(8, MT), NTHREADS, SMEM_GEMM>>>(
        pln21, pw12, fc1_b, nullptr, nullptr, phid1, HID, DIM, 0);

    // 7. fc2 (A single, B split) + residual -> out
    gemm2<EPI_FC2, 0, 1><<<dim3(2, MT), NTHREADS, SMEM_GEMM>>>(
        phid1, pw22, fc2_b, px2, out, nullptr, DIM, HID, 0);
}

// round 12
// speedup vs baseline: 1.2316x; 1.2316x over previous
#include <cuda_runtime.h>
#include <cuda_bf16.h>
#include <mma.h>
#include <math.h>
#include <cstdint>

using namespace nvcuda;

// ---------------- problem constants ----------------
static constexpr int BB    = 4;
static constexpr int HH    = 192;
static constexpr int WW    = 192;
static constexpr int DIM   = 256;
static constexpr int HEADS = 8;
static constexpr int HD    = 32;
static constexpr int WIN   = 8;
static constexpr int SHIFT = 4;
static constexpr int HID   = 1024;

static constexpr int L     = HH * WW;          // 36864
static constexpr int MROWS = BB * L;           // 147456
static constexpr int NWB   = HH / WIN;         // 24
static constexpr int NWIN  = BB * NWB * NWB;   // 2304
static constexpr float SCALE = 0.17677669529663687f; // 1/sqrt(32)

// ---------------- scratch ----------------
// h2: LN1 out, 2-component [M][2K]=[hi|lo] (qk GEMM 3-term; v GEMM 2-term A-split).
// attn1/ln21/hid1: single bf16. proj/fc1/fc2 are 1-term (A_hi*B_hi) — errors diluted
// by residual adds (calibrated at ~2.2e-4 per dropped term).
__device__ __nv_bfloat16 g_h2   [(size_t)MROWS * 2 * DIM];
__device__ float         g_qkv  [(size_t)MROWS * 3 * DIM];   // fp32 (attention reads tf32)
__device__ __nv_bfloat16 g_attn1[(size_t)MROWS * DIM];
__device__ float         g_x2   [(size_t)MROWS * DIM];
__device__ __nv_bfloat16 g_ln21 [(size_t)MROWS * DIM];
__device__ __nv_bfloat16 g_hid1 [(size_t)MROWS * HID];

__device__ __nv_bfloat16 g_wqkv2 [2 * DIM * 3 * DIM];   // split (qk uses lo rows)
__device__ __nv_bfloat16 g_wproj1[DIM * DIM];           // hi only
__device__ __nv_bfloat16 g_wfc11 [DIM * HID];           // hi only
__device__ __nv_bfloat16 g_wfc21 [HID * DIM];           // hi only

__device__ __forceinline__ void split2(float v, __nv_bfloat16& hi, __nv_bfloat16& lo) {
    hi = __float2bfloat16(v);
    lo = __float2bfloat16(v - __bfloat162float(hi));
}

__device__ __forceinline__ int win_row_to_token(int r) {
    int widx = r >> 6;
    int t    = r & 63;
    int b    = widx / (NWB * NWB);
    int wrem = widx - b * (NWB * NWB);
    int wh   = wrem / NWB;
    int ww   = wrem - wh * NWB;
    int ty   = t >> 3, tx = t & 7;
    int hp   = wh * WIN + ty + SHIFT; if (hp >= HH) hp -= HH;
    int wp   = ww * WIN + tx + SHIFT; if (wp >= WW) wp -= WW;
    return b * L + hp * WW + wp;
}

// ---------------- weight conversion (one launch) ----------------
// qkv: split [2K][N]; proj/fc1/fc2: hi-only [K][N]
__global__ void cvt_all(const float* __restrict__ qkv_w, const float* __restrict__ proj_w,
                        const float* __restrict__ fc1_w, const float* __restrict__ fc2_w,
                        __nv_bfloat16* __restrict__ wq, __nv_bfloat16* __restrict__ wp,
                        __nv_bfloat16* __restrict__ w1, __nv_bfloat16* __restrict__ w2) {
    int i = blockIdx.x * blockDim.x + threadIdx.x;
    int j = i;
    if (j < 196608) {
        __nv_bfloat16 hi, lo;
        split2(qkv_w[j], hi, lo);
        wq[j]          = hi;
        wq[196608 + j] = lo;
        return;
    }
    j -= 196608;
    if (j < 65536)  { wp[j] = __float2bfloat16(proj_w[j]); return; }
    j -= 65536;
    if (j < 262144) { w1[j] = __float2bfloat16(fc1_w[j]); return; }
    j -= 262144;
    if (j < 262144) { w2[j] = __float2bfloat16(fc2_w[j]); }
}

// ---------------- LayerNorm fp32 -> split bf16 [M][2K] (LN1) ----------------
__global__ void ln_split_kernel(const float* __restrict__ x, const float* __restrict__ g,
                                const float* __restrict__ b, __nv_bfloat16* __restrict__ out) {
    int gw   = (blockIdx.x * blockDim.x + threadIdx.x) >> 5;
    int lane = threadIdx.x & 31;
    const float4* rp = (const float4*)(x + (size_t)gw * DIM);
    float4 a0 = rp[lane * 2], a1 = rp[lane * 2 + 1];
    float s  = a0.x + a0.y + a0.z + a0.w + a1.x + a1.y + a1.z + a1.w;
    float sq = a0.x*a0.x + a0.y*a0.y + a0.z*a0.z + a0.w*a0.w
             + a1.x*a1.x + a1.y*a1.y + a1.z*a1.z + a1.w*a1.w;
    #pragma unroll
    for (int o = 16; o; o >>= 1) {
        s  += __shfl_xor_sync(0xffffffffu, s,  o);
        sq += __shfl_xor_sync(0xffffffffu, sq, o);
    }
    float mean = s * (1.0f / DIM);
    float var  = sq * (1.0f / DIM) - mean * mean;
    float rstd = rsqrtf(var + 1e-5f);
    const float4* gp = (const float4*)g;
    const float4* bp = (const float4*)b;
    float4 g0 = gp[lane*2], g1 = gp[lane*2+1], b0 = bp[lane*2], b1 = bp[lane*2+1];
    float y[8];
    y[0] = (a0.x - mean) * rstd * g0.x + b0.x;
    y[1] = (a0.y - mean) * rstd * g0.y + b0.y;
    y[2] = (a0.z - mean) * rstd * g0.z + b0.z;
    y[3] = (a0.w - mean) * rstd * g0.w + b0.w;
    y[4] = (a1.x - mean) * rstd * g1.x + b1.x;
    y[5] = (a1.y - mean) * rstd * g1.y + b1.y;
    y[6] = (a1.z - mean) * rstd * g1.z + b1.z;
    y[7] = (a1.w - mean) * rstd * g1.w + b1.w;
    __nv_bfloat16 hi[8], lo[8];
    #pragma unroll
    for (int i = 0; i < 8; i++) split2(y[i], hi[i], lo[i]);
    __nv_bfloat16* base = out + (size_t)gw * (2 * DIM) + lane * 8;
    *(uint4*)(base)       = *(uint4*)hi;
    *(uint4*)(base + DIM) = *(uint4*)lo;
}

// ---------------- LayerNorm fp32 -> single bf16 [M][K] (LN2) ----------------
__global__ void ln_single_kernel(const float* __restrict__ x, const float* __restrict__ g,
                                 const float* __restrict__ b, __nv_bfloat16* __restrict__ out) {
    int gw   = (blockIdx.x * blockDim.x + threadIdx.x) >> 5;
    int lane = threadIdx.x & 31;
    const float4* rp = (const float4*)(x + (size_t)gw * DIM);
    float4 a0 = rp[lane * 2], a1 = rp[lane * 2 + 1];
    float s  = a0.x + a0.y + a0.z + a0.w + a1.x + a1.y + a1.z + a1.w;
    float sq = a0.x*a0.x + a0.y*a0.y + a0.z*a0.z + a0.w*a0.w
             + a1.x*a1.x + a1.y*a1.y + a1.z*a1.z + a1.w*a1.w;
    #pragma unroll
    for (int o = 16; o; o >>= 1) {
        s  += __shfl_xor_sync(0xffffffffu, s,  o);
        sq += __shfl_xor_sync(0xffffffffu, sq, o);
    }
    float mean = s * (1.0f / DIM);
    float var  = sq * (1.0f / DIM) - mean * mean;
    float rstd = rsqrtf(var + 1e-5f);
    const float4* gp = (const float4*)g;
    const float4* bp = (const float4*)b;
    float4 g0 = gp[lane*2], g1 = gp[lane*2+1], b0 = bp[lane*2], b1 = bp[lane*2+1];
    __nv_bfloat16 h[8];
    h[0] = __float2bfloat16((a0.x - mean) * rstd * g0.x + b0.x);
    h[1] = __float2bfloat16((a0.y - mean) * rstd * g0.y + b0.y);
    h[2] = __float2bfloat16((a0.z - mean) * rstd * g0.z + b0.z);
    h[3] = __float2bfloat16((a0.w - mean) * rstd * g0.w + b0.w);
    h[4] = __float2bfloat16((a1.x - mean) * rstd * g1.x + b1.x);
    h[5] = __float2bfloat16((a1.y - mean) * rstd * g1.y + b1.y);
    h[6] = __float2bfloat16((a1.z - mean) * rstd * g1.z + b1.z);
    h[7] = __float2bfloat16((a1.w - mean) * rstd * g1.w + b1.w);
    *(uint4*)(out + (size_t)gw * DIM + lane * 8) = *(uint4*)h;
}

// ---------------- GEMM: bf16 wmma, 64x64 warp tiles, 3-stage pipeline ----------------
// A2: load+use A_lo (A stored [M][KA] with lo at +K). B2: load+use B_lo rows.
// KA passed explicitly (v-GEMM reads hi half of a split buffer).
static constexpr int Bb_M = 128, Bb_N = 128, Bb_K = 32, STAGES = 3;
static constexpr int NTHREADS = 128;
static constexpr int LDA = Bb_K + 8;     // 40
static constexpr int LDB = Bb_N + 8;     // 136
static constexpr int AH_ST = Bb_M * LDA; // 5120
static constexpr int BH_ST = Bb_K * LDB; // 4352
static constexpr int STAGE_E = 2 * AH_ST + 2 * BH_ST;   // 18944 elems
static constexpr int LDC_S = 132;
static constexpr int SMEM_GEMM = STAGES * STAGE_E * 2;  // 113664 B

static constexpr int EPI_QKV = 0, EPI_PROJ = 1, EPI_FC1 = 2, EPI_FC2 = 3;

__device__ __forceinline__ void cpa16(void* sptr, const void* gptr) {
    unsigned int s = (unsigned int)__cvta_generic_to_shared(sptr);
    asm volatile("cp.async.cg.shared.global [%0], [%1], 16;\n" :: "r"(s), "l"(gptr));
}

template<int EPI, int A2, int B2>
__global__ void __launch_bounds__(NTHREADS, 2)
gemm2(const __nv_bfloat16* __restrict__ A,      // [M][KA]
      const __nv_bfloat16* __restrict__ Bm,     // [B2?2K:K][N]
      const float* __restrict__ bias,
      const float* __restrict__ res,
      float* __restrict__ outF,
      __nv_bfloat16* __restrict__ outH,
      int N, int K, int KA, int nOff) {
    extern __shared__ char smem[];
    __nv_bfloat16* sm = (__nv_bfloat16*)smem;
    float*         Cs = (float*)smem;

    int tid  = threadIdx.x;
    int warp = tid >> 5;
    int wm   = warp >> 1;
    int wn   = warp & 1;
    int bn   = nOff + blockIdx.x * Bb_N;
    int bm   = blockIdx.y * Bb_M;
    int T    = K / Bb_K;

    wmma::fragment<wmma::accumulator, 16, 16, 16, float> acc[4][4];
    #pragma unroll
    for (int i = 0; i < 4; i++)
        #pragma unroll
        for (int j = 0; j < 4; j++)
            wmma::fill_fragment(acc[i][j], 0.0f);

    auto loads = [&](int t) {
        int k0 = t * Bb_K;
        int st = t % STAGES;
        __nv_bfloat16* AH = sm + st * STAGE_E;
        __nv_bfloat16* AL = AH + AH_ST;
        __nv_bfloat16* BH = AL + AH_ST;
        __nv_bfloat16* BL = BH + BH_ST;
        #pragma unroll
        for (int i = 0; i < 4; i++) {
            int c = tid + i * NTHREADS;
            int r = c >> 2, cc = (c & 3) * 8;
            const __nv_bfloat16* src = A + (size_t)(bm + r) * KA + k0 + cc;
            cpa16(&AH[r * LDA + cc], src);
            if (A2) cpa16(&AL[r * LDA + cc], src + K);
        }
        #pragma unroll
        for (int i = 0; i < 4; i++) {
            int c = tid + i * NTHREADS;
            int r = c >> 4, cc = (c & 15) * 8;
            cpa16(&BH[r * LDB + cc], Bm + (size_t)(k0 + r) * N + bn + cc);
            if (B2)
                cpa16(&BL[r * LDB + cc], Bm + (size_t)(K + k0 + r) * N + bn + cc);
        }
        asm volatile("cp.async.commit_group;\n" ::);
    };

    loads(0);
    loads(1);

    for (int t = 0; t < T; t++) {
        asm volatile("cp.async.wait_group 1;\n" ::);
        __syncthreads();
        if (t + 2 < T) loads(t + 2);

        int st = t % STAGES;
        const __nv_bfloat16* AH = sm + st * STAGE_E;
        const __nv_bfloat16* AL = AH + AH_ST;
        const __nv_bfloat16* BH = AL + AH_ST;
        const __nv_bfloat16* BL = BH + BH_ST;

        #pragma unroll
        for (int kk = 0; kk < Bb_K; kk += 16) {
            wmma::fragment<wmma::matrix_a, 16, 16, 16, __nv_bfloat16, wmma::row_major> ah[4], al[4];
            wmma::fragment<wmma::matrix_b, 16, 16, 16, __nv_bfloat16, wmma::row_major> bf[4];
            #pragma unroll
            for (int i = 0; i < 4; i++) {
                wmma::load_matrix_sync(ah[i], &AH[(wm * 64 + i * 16) * LDA + kk], LDA);
                if (A2)
                    wmma::load_matrix_sync(al[i], &AL[(wm * 64 + i * 16) * LDA + kk], LDA);
            }
            #pragma unroll
            for (int j = 0; j < 4; j++)
                wmma::load_matrix_sync(bf[j], &BH[kk * LDB + wn * 64 + j * 16], LDB);
            #pragma unroll
            for (int i = 0; i < 4; i++)
                #pragma unroll
                for (int j = 0; j < 4; j++) {
                    wmma::mma_sync(acc[i][j], ah[i], bf[j], acc[i][j]);
                    if (A2) wmma::mma_sync(acc[i][j], al[i], bf[j], acc[i][j]);
                }
            if (B2) {
                #pragma unroll
                for (int j = 0; j < 4; j++)
                    wmma::load_matrix_sync(bf[j], &BL[kk * LDB + wn * 64 + j * 16], LDB);
                #pragma unroll
                for (int i = 0; i < 4; i++)
                    #pragma unroll
                    for (int j = 0; j < 4; j++)
                        wmma::mma_sync(acc[i][j], ah[i], bf[j], acc[i][j]);
            }
        }
    }

    asm volatile("cp.async.wait_all;\n" ::);
    __syncthreads();

    #pragma unroll
    for (int i = 0; i < 4; i++)
        #pragma unroll
        for (int j = 0; j < 4; j++)
            wmma::store_matrix_sync(&Cs[(wm * 64 + i * 16) * LDC_S + wn * 64 + j * 16],
                                    acc[i][j], LDC_S, wmma::mem_row_major);
    __syncthreads();

    #pragma unroll 4
    for (int e = 0; e < 32; e++) {
        int idx = tid + e * NTHREADS;
        int r = idx >> 5;
        int c = (idx & 31) * 4;
        float4 v = *(float4*)&Cs[r * LDC_S + c];
        int gr = bm + r, gc = bn + c;
        float4 bv = *(const float4*)(bias + gc);
        if (EPI == EPI_QKV) {
            float4 o = {v.x + bv.x, v.y + bv.y, v.z + bv.z, v.w + bv.w};
            *(float4*)(outF + (size_t)gr * N + gc) = o;
        } else if (EPI == EPI_PROJ) {
            int tok = win_row_to_token(gr);
            size_t off = (size_t)tok * DIM + gc;
            float4 rv = *(const float4*)(res + off);
            float4 o = {v.x + bv.x + rv.x, v.y + bv.y + rv.y,
                        v.z + bv.z + rv.z, v.w + bv.w + rv.w};
            *(float4*)(outF + off) = o;
        } else if (EPI == EPI_FC1) {
            float tv[4] = {v.x + bv.x, v.y + bv.y, v.z + bv.z, v.w + bv.w};
            __nv_bfloat16 h[4];
            #pragma unroll
            for (int q = 0; q < 4; q++)
                h[q] = __float2bfloat16(0.5f * tv[q] * (1.0f + erff(tv[q] * 0.70710678118654752f)));
            *(uint2*)(outH + (size_t)gr * HID + gc) = *(uint2*)h;
        } else { // EPI_FC2
            size_t off = (size_t)gr * N + gc;
            float4 rv = *(const float4*)(res + off);
            float4 o = {v.x + bv.x + rv.x, v.y + bv.y + rv.y,
                        v.z + bv.z + rv.z, v.w + bv.w + rv.w};
            *(float4*)(outF + off) = o;
        }
    }
}

// ---------------- attention: tf32 wmma, one block per (window, head), 128 threads ----------------
static constexpr int AQ_LD = 36;
static constexpr int AS_LD = 64;
static constexpr int OFF_Q = 0;
static constexpr int OFF_K = OFF_Q + 64 * AQ_LD;     // 2304
static constexpr int OFF_V = OFF_K + 64 * AQ_LD;     // 4608
static constexpr int OFF_S = OFF_V + 64 * AQ_LD;     // 6912
static constexpr int OFF_B = OFF_S + 64 * AS_LD;     // 11008
static constexpr int OFF_T = OFF_B + 228;            // 11236
static constexpr int ATT_SMEM = (OFF_T + 64) * 4;    // 45200 B

template<class Frag>
__device__ __forceinline__ void to_tf32(Frag& f) {
    #pragma unroll
    for (int t = 0; t < f.num_elements; t++) f.x[t] = wmma::__float_to_tf32(f.x[t]);
}

__global__ void attn_kernel(const float* __restrict__ qkv,
                            const float* __restrict__ table,
                            __nv_bfloat16* __restrict__ out1) {
    extern __shared__ float sm[];
    float* sQ = sm + OFF_Q;
    float* sK = sm + OFF_K;
    float* sV = sm + OFF_V;
    float* sS = sm + OFF_S;
    float* sB = sm + OFF_B;
    int*   sTok = (int*)(sm + OFF_T);

    int widx = blockIdx.x, head = blockIdx.y;
    int tid = threadIdx.x, lane = tid & 31, w = tid >> 5;

    if (tid < 225) sB[tid] = table[tid * HEADS + head];
    if (tid < 64)  sTok[tid] = win_row_to_token(widx * 64 + tid);
    __syncthreads();

    #pragma unroll
    for (int i = 0; i < 4; i++) {
        int c = tid + i * 128;
        int r = c >> 3, cc = (c & 7) * 4;
        size_t base = (size_t)sTok[r] * (3 * DIM) + head * HD + cc;
        *(float4*)&sQ[r * AQ_LD + cc] = *(const float4*)&qkv[base];
        *(float4*)&sK[r * AQ_LD + cc] = *(const float4*)&qkv[base + DIM];
        *(float4*)&sV[r * AQ_LD + cc] = *(const float4*)&qkv[base + 2 * DIM];
    }
    __syncthreads();

    // S = Q @ K^T  (warp w -> rows [w*16, w*16+16))
    {
        wmma::fragment<wmma::accumulator, 16, 16, 8, float> acc[4];
        #pragma unroll
        for (int j = 0; j < 4; j++) wmma::fill_fragment(acc[j], 0.0f);
        #pragma unroll
        for (int kk = 0; kk < 32; kk += 8) {
            wmma::fragment<wmma::matrix_a, 16, 16, 8, wmma::precision::tf32, wmma::row_major> af;
            wmma::load_matrix_sync(af, &sQ[(w * 16) * AQ_LD + kk], AQ_LD);
            to_tf32(af);
            #pragma unroll
            for (int j = 0; j < 4; j++) {
                wmma::fragment<wmma::matrix_b, 16, 16, 8, wmma::precision::tf32, wmma::col_major> bf;
                wmma::load_matrix_sync(bf, &sK[(j * 16) * AQ_LD + kk], AQ_LD);
                to_tf32(bf);
                wmma::mma_sync(acc[j], af, bf, acc[j]);
            }
        }
        #pragma unroll
        for (int j = 0; j < 4; j++)
            wmma::store_matrix_sync(&sS[(w * 16) * AS_LD + j * 16], acc[j], AS_LD, wmma::mem_row_major);
    }

    // softmax in place (warp-local rows)
    #pragma unroll 2
    for (int rr = 0; rr < 16; rr++) {
        int r = w * 16 + rr;
        int yi = r >> 3, xi = r & 7;
        int c0 = lane, c1 = lane + 32;
        int i0 = (yi - (c0 >> 3) + 7) * 15 + (xi - (c0 & 7) + 7);
        int i1 = (yi - (c1 >> 3) + 7) * 15 + (xi - (c1 & 7) + 7);
        float v0 = sS[r * AS_LD + c0] * SCALE + sB[i0];
        float v1 = sS[r * AS_LD + c1] * SCALE + sB[i1];
        float m = fmaxf(v0, v1);
        #pragma unroll
        for (int o = 16; o; o >>= 1) m = fmaxf(m, __shfl_xor_sync(0xffffffffu, m, o));
        float e0 = __expf(v0 - m), e1 = __expf(v1 - m);
        float s = e0 + e1;
        #pragma unroll
        for (int o = 16; o; o >>= 1) s += __shfl_xor_sync(0xffffffffu, s, o);
        float inv = 1.0f / s;
        sS[r * AS_LD + c0] = e0 * inv;
        sS[r * AS_LD + c1] = e1 * inv;
    }
    __syncwarp();

    // O = P @ V (warp-local rows)
    {
        wmma::fragment<wmma::accumulator, 16, 16, 8, float> acc[2];
        #pragma unroll
        for (int j = 0; j < 2; j++) wmma::fill_fragment(acc[j], 0.0f);
        #pragma unroll
        for (int k0 = 0; k0 < 64; k0 += 8) {
            wmma::fragment<wmma::matrix_a, 16, 16, 8, wmma::precision::tf32, wmma::row_major> af;
            wmma::load_matrix_sync(af, &sS[(w * 16) * AS_LD + k0], AS_LD);
            to_tf32(af);
            #pragma unroll
            for (int j = 0; j < 2; j++) {
                wmma::fragment<wmma::matrix_b, 16, 16, 8, wmma::precision::tf32, wmma::row_major> bf;
                wmma::load_matrix_sync(bf, &sV[k0 * AQ_LD + j * 16], AQ_LD);
                to_tf32(bf);
                wmma::mma_sync(acc[j], af, bf, acc[j]);
            }
        }
        #pragma unroll
        for (int j = 0; j < 2; j++)
            wmma::store_matrix_sync(&sS[(w * 16) * AS_LD + j * 16], acc[j], AS_LD, wmma::mem_row_major);
    }
    __syncthreads();

    // write O (windowed order), single bf16 (proj is 1-term)
    #pragma unroll
    for (int i = 0; i < 16; i++) {
        int idx = tid + i * 128;
        int r = idx >> 5, c = idx & 31;
        out1[((size_t)widx * 64 + r) * DIM + head * HD + c] =
            __float2bfloat16(sS[r * AS_LD + c]);
    }
}

// ---------------- launch ----------------
extern "C" void kernel_launch(void* const* d_in, const int* in_sizes, int n_in,
                              void* d_out, int out_size) {
    const float* x        = (const float*)d_in[0];
    const float* norm1_g  = (const float*)d_in[1];
    const float* norm1_b  = (const float*)d_in[2];
    const float* qkv_w    = (const float*)d_in[3];
    const float* qkv_b    = (const float*)d_in[4];
    const float* bias_tab = (const float*)d_in[5];
    const float* proj_w   = (const float*)d_in[6];
    const float* proj_b   = (const float*)d_in[7];
    const float* norm2_g  = (const float*)d_in[8];
    const float* norm2_b  = (const float*)d_in[9];
    const float* fc1_w    = (const float*)d_in[10];
    const float* fc1_b    = (const float*)d_in[11];
    const float* fc2_w    = (const float*)d_in[12];
    const float* fc2_b    = (const float*)d_in[13];
    float* out            = (float*)d_out;

    void *p;
    cudaGetSymbolAddress(&p, g_h2);    __nv_bfloat16* ph2   = (__nv_bfloat16*)p;
    cudaGetSymbolAddress(&p, g_qkv);   float*         pqkv  = (float*)p;
    cudaGetSymbolAddress(&p, g_attn1); __nv_bfloat16* pat1  = (__nv_bfloat16*)p;
    cudaGetSymbolAddress(&p, g_x2);    float*         px2   = (float*)p;
    cudaGetSymbolAddress(&p, g_ln21);  __nv_bfloat16* pln21 = (__nv_bfloat16*)p;
    cudaGetSymbolAddress(&p, g_hid1);  __nv_bfloat16* phid1 = (__nv_bfloat16*)p;
    cudaGetSymbolAddress(&p, g_wqkv2); __nv_bfloat16* pwq2  = (__nv_bfloat16*)p;
    cudaGetSymbolAddress(&p, g_wproj1);__nv_bfloat16* pwp1  = (__nv_bfloat16*)p;
    cudaGetSymbolAddress(&p, g_wfc11); __nv_bfloat16* pw11  = (__nv_bfloat16*)p;
    cudaGetSymbolAddress(&p, g_wfc21); __nv_bfloat16* pw21  = (__nv_bfloat16*)p;

    cudaFuncSetAttribute((const void*)gemm2<EPI_QKV, 1, 1>,  cudaFuncAttributeMaxDynamicSharedMemorySize, SMEM_GEMM);
    cudaFuncSetAttribute((const void*)gemm2<EPI_QKV, 1, 0>,  cudaFuncAttributeMaxDynamicSharedMemorySize, SMEM_GEMM);
    cudaFuncSetAttribute((const void*)gemm2<EPI_PROJ, 0, 0>, cudaFuncAttributeMaxDynamicSharedMemorySize, SMEM_GEMM);
    cudaFuncSetAttribute((const void*)gemm2<EPI_FC1, 0, 0>,  cudaFuncAttributeMaxDynamicSharedMemorySize, SMEM_GEMM);
    cudaFuncSetAttribute((const void*)gemm2<EPI_FC2, 0, 0>,  cudaFuncAttributeMaxDynamicSharedMemorySize, SMEM_GEMM);
    cudaFuncSetAttribute(attn_kernel, cudaFuncAttributeMaxDynamicSharedMemorySize, ATT_SMEM);

    const int MT = MROWS / Bb_M;   // 1152

    // 0. weights
    cvt_all<<<(786432 + 255)/256, 256>>>(qkv_w, proj_w, fc1_w, fc2_w, pwq2, pwp1, pw11, pw21);

    // 1. LN1 -> h2 (2-component)
    ln_split_kernel<<<MROWS/8, 256>>>(x, norm1_g, norm1_b, ph2);

    // 2a. QKV q,k columns (N [0,512), 3-term) -> qkv f32
    gemm2<EPI_QKV, 1, 1><<<dim3(4, MT), NTHREADS, SMEM_GEMM>>>(
        ph2, pwq2, qkv_b, nullptr, pqkv, nullptr, 3*DIM, DIM, 2*DIM, 0);
    // 2b. QKV v columns (N [512,768), 2-term A-split)
    gemm2<EPI_QKV, 1, 0><<<dim3(2, MT), NTHREADS, SMEM_GEMM>>>(
        ph2, pwq2, qkv_b, nullptr, pqkv, nullptr, 3*DIM, DIM, 2*DIM, 512);

    // 3. windowed attention (tf32) -> attn1 (single bf16, windowed order)
    attn_kernel<<<dim3(NWIN, HEADS), 128, ATT_SMEM>>>(pqkv, bias_tab, pat1);

    // 4. proj (1-term) + shortcut scatter -> x2
    gemm2<EPI_PROJ, 0, 0><<<dim3(2, MT), NTHREADS, SMEM_GEMM>>>(
        pat1, pwp1, proj_b, x, px2, nullptr, DIM, DIM, DIM, 0);

    // 5. LN2 -> ln21 (single)
    ln_single_kernel<<<MROWS/8, 256>>>(px2, norm2_g, norm2_b, pln21);

    // 6. fc1 (1-term) + GELU -> hid1
    gemm2<EPI_FC1, 0, 0><<<dim3(8, MT), NTHREADS, SMEM_GEMM>>>(
        pln21, pw11, fc1_b, nullptr, nullptr, phid1, HID, DIM, DIM, 0);

    // 7. fc2 (1-term) + residual -> out
    gemm2<EPI_FC2, 0, 0><<<dim3(2, MT), NTHREADS, SMEM_GEMM>>>(
        phid1, pw21, fc2_b, px2, out, nullptr, DIM, HID, HID, 0);
}

// round 13
// speedup vs baseline: 1.2343x; 1.0021x over previous
#include <cuda_runtime.h>
#include <cuda_bf16.h>
#include <mma.h>
#include <math.h>
#include <cstdint>

using namespace nvcuda;

// ---------------- problem constants ----------------
static constexpr int BB    = 4;
static constexpr int HH    = 192;
static constexpr int WW    = 192;
static constexpr int DIM   = 256;
static constexpr int HEADS = 8;
static constexpr int HD    = 32;
static constexpr int WIN   = 8;
static constexpr int SHIFT = 4;
static constexpr int HID   = 1024;

static constexpr int L     = HH * WW;          // 36864
static constexpr int MROWS = BB * L;           // 147456
static constexpr int NWB   = HH / WIN;         // 24
static constexpr int NWIN  = BB * NWB * NWB;   // 2304
static constexpr float SCALE = 0.17677669529663687f; // 1/sqrt(32)

// ---------------- scratch ----------------
// h2: LN1 out, 2-component [M][2K]=[hi|lo] (qk GEMM 3-term; v GEMM 2-term A-split).
// attn1/ln21/hid1: single bf16. proj/fc1/fc2 are 1-term (A_hi*B_hi) — errors diluted
// by residual adds (calibrated at ~2.2e-4 per dropped term).
__device__ __nv_bfloat16 g_h2   [(size_t)MROWS * 2 * DIM];
__device__ float         g_qkv  [(size_t)MROWS * 3 * DIM];   // fp32 (attention reads tf32)
__device__ __nv_bfloat16 g_attn1[(size_t)MROWS * DIM];
__device__ float         g_x2   [(size_t)MROWS * DIM];
__device__ __nv_bfloat16 g_ln21 [(size_t)MROWS * DIM];
__device__ __nv_bfloat16 g_hid1 [(size_t)MROWS * HID];

__device__ __nv_bfloat16 g_wqkv2 [2 * DIM * 3 * DIM];   // split (qk uses lo rows)
__device__ __nv_bfloat16 g_wproj1[DIM * DIM];           // hi only
__device__ __nv_bfloat16 g_wfc11 [DIM * HID];           // hi only
__device__ __nv_bfloat16 g_wfc21 [HID * DIM];           // hi only

__device__ __forceinline__ void split2(float v, __nv_bfloat16& hi, __nv_bfloat16& lo) {
    hi = __float2bfloat16(v);
    lo = __float2bfloat16(v - __bfloat162float(hi));
}

__device__ __forceinline__ int win_row_to_token(int r) {
    int widx = r >> 6;
    int t    = r & 63;
    int b    = widx / (NWB * NWB);
    int wrem = widx - b * (NWB * NWB);
    int wh   = wrem / NWB;
    int ww   = wrem - wh * NWB;
    int ty   = t >> 3, tx = t & 7;
    int hp   = wh * WIN + ty + SHIFT; if (hp >= HH) hp -= HH;
    int wp   = ww * WIN + tx + SHIFT; if (wp >= WW) wp -= WW;
    return b * L + hp * WW + wp;
}

// ---------------- weight conversion (one launch) ----------------
// qkv: split [2K][N]; proj/fc1/fc2: hi-only [K][N]
__global__ void cvt_all(const float* __restrict__ qkv_w, const float* __restrict__ proj_w,
                        const float* __restrict__ fc1_w, const float* __restrict__ fc2_w,
                        __nv_bfloat16* __restrict__ wq, __nv_bfloat16* __restrict__ wp,
                        __nv_bfloat16* __restrict__ w1, __nv_bfloat16* __restrict__ w2) {
    int i = blockIdx.x * blockDim.x + threadIdx.x;
    int j = i;
    if (j < 196608) {
        __nv_bfloat16 hi, lo;
        split2(qkv_w[j], hi, lo);
        wq[j]          = hi;
        wq[196608 + j] = lo;
        return;
    }
    j -= 196608;
    if (j < 65536)  { wp[j] = __float2bfloat16(proj_w[j]); return; }
    j -= 65536;
    if (j < 262144) { w1[j] = __float2bfloat16(fc1_w[j]); return; }
    j -= 262144;
    if (j < 262144) { w2[j] = __float2bfloat16(fc2_w[j]); }
}

// ---------------- LayerNorm fp32 -> split bf16 [M][2K] (LN1) ----------------
__global__ void ln_split_kernel(const float* __restrict__ x, const float* __restrict__ g,
                                const float* __restrict__ b, __nv_bfloat16* __restrict__ out) {
    int gw   = (blockIdx.x * blockDim.x + threadIdx.x) >> 5;
    int lane = threadIdx.x & 31;
    const float4* rp = (const float4*)(x + (size_t)gw * DIM);
    float4 a0 = rp[lane * 2], a1 = rp[lane * 2 + 1];
    float s  = a0.x + a0.y + a0.z + a0.w + a1.x + a1.y + a1.z + a1.w;
    float sq = a0.x*a0.x + a0.y*a0.y + a0.z*a0.z + a0.w*a0.w
             + a1.x*a1.x + a1.y*a1.y + a1.z*a1.z + a1.w*a1.w;
    #pragma unroll
    for (int o = 16; o; o >>= 1) {
        s  += __shfl_xor_sync(0xffffffffu, s,  o);
        sq += __shfl_xor_sync(0xffffffffu, sq, o);
    }
    float mean = s * (1.0f / DIM);
    float var  = sq * (1.0f / DIM) - mean * mean;
    float rstd = rsqrtf(var + 1e-5f);
    const float4* gp = (const float4*)g;
    const float4* bp = (const float4*)b;
    float4 g0 = gp[lane*2], g1 = gp[lane*2+1], b0 = bp[lane*2], b1 = bp[lane*2+1];
    float y[8];
    y[0] = (a0.x - mean) * rstd * g0.x + b0.x;
    y[1] = (a0.y - mean) * rstd * g0.y + b0.y;
    y[2] = (a0.z - mean) * rstd * g0.z + b0.z;
    y[3] = (a0.w - mean) * rstd * g0.w + b0.w;
    y[4] = (a1.x - mean) * rstd * g1.x + b1.x;
    y[5] = (a1.y - mean) * rstd * g1.y + b1.y;
    y[6] = (a1.z - mean) * rstd * g1.z + b1.z;
    y[7] = (a1.w - mean) * rstd * g1.w + b1.w;
    __nv_bfloat16 hi[8], lo[8];
    #pragma unroll
    for (int i = 0; i < 8; i++) split2(y[i], hi[i], lo[i]);
    __nv_bfloat16* base = out + (size_t)gw * (2 * DIM) + lane * 8;
    *(uint4*)(base)       = *(uint4*)hi;
    *(uint4*)(base + DIM) = *(uint4*)lo;
}

// ---------------- LayerNorm fp32 -> single bf16 [M][K] (LN2) ----------------
__global__ void ln_single_kernel(const float* __restrict__ x, const float* __restrict__ g,
                                 const float* __restrict__ b, __nv_bfloat16* __restrict__ out) {
    int gw   = (blockIdx.x * blockDim.x + threadIdx.x) >> 5;
    int lane = threadIdx.x & 31;
    const float4* rp = (const float4*)(x + (size_t)gw * DIM);
    float4 a0 = rp[lane * 2], a1 = rp[lane * 2 + 1];
    float s  = a0.x + a0.y + a0.z + a0.w + a1.x + a1.y + a1.z + a1.w;
    float sq = a0.x*a0.x + a0.y*a0.y + a0.z*a0.z + a0.w*a0.w
             + a1.x*a1.x + a1.y*a1.y + a1.z*a1.z + a1.w*a1.w;
    #pragma unroll
    for (int o = 16; o; o >>= 1) {
        s  += __shfl_xor_sync(0xffffffffu, s,  o);
        sq += __shfl_xor_sync(0xffffffffu, sq, o);
    }
    float mean = s * (1.0f / DIM);
    float var  = sq * (1.0f / DIM) - mean * mean;
    float rstd = rsqrtf(var + 1e-5f);
    const float4* gp = (const float4*)g;
    const float4* bp = (const float4*)b;
    float4 g0 = gp[lane*2], g1 = gp[lane*2+1], b0 = bp[lane*2], b1 = bp[lane*2+1];
    __nv_bfloat16 h[8];
    h[0] = __float2bfloat16((a0.x - mean) * rstd * g0.x + b0.x);
    h[1] = __float2bfloat16((a0.y - mean) * rstd * g0.y + b0.y);
    h[2] = __float2bfloat16((a0.z - mean) * rstd * g0.z + b0.z);
    h[3] = __float2bfloat16((a0.w - mean) * rstd * g0.w + b0.w);
    h[4] = __float2bfloat16((a1.x - mean) * rstd * g1.x + b1.x);
    h[5] = __float2bfloat16((a1.y - mean) * rstd * g1.y + b1.y);
    h[6] = __float2bfloat16((a1.z - mean) * rstd * g1.z + b1.z);
    h[7] = __float2bfloat16((a1.w - mean) * rstd * g1.w + b1.w);
    *(uint4*)(out + (size_t)gw * DIM + lane * 8) = *(uint4*)h;
}

// ---------------- GEMM: bf16 wmma, 64x64 warp tiles, 3-stage pipeline ----------------
// A2: load+use A_lo (A stored [M][KA] with lo at +K). B2: load+use B_lo rows.
// KA passed explicitly (v-GEMM reads hi half of a split buffer).
static constexpr int Bb_M = 128, Bb_N = 128, Bb_K = 32, STAGES = 3;
static constexpr int NTHREADS = 128;
static constexpr int LDA = Bb_K + 8;     // 40
static constexpr int LDB = Bb_N + 8;     // 136
static constexpr int AH_ST = Bb_M * LDA; // 5120
static constexpr int BH_ST = Bb_K * LDB; // 4352
static constexpr int STAGE_E = 2 * AH_ST + 2 * BH_ST;   // 18944 elems
static constexpr int LDC_S = 132;
static constexpr int SMEM_GEMM = STAGES * STAGE_E * 2;  // 113664 B

static constexpr int EPI_QKV = 0, EPI_PROJ = 1, EPI_FC1 = 2, EPI_FC2 = 3;

__device__ __forceinline__ void cpa16(void* sptr, const void* gptr) {
    unsigned int s = (unsigned int)__cvta_generic_to_shared(sptr);
    asm volatile("cp.async.cg.shared.global [%0], [%1], 16;\n" :: "r"(s), "l"(gptr));
}

template<int EPI, int A2, int B2>
__global__ void __launch_bounds__(NTHREADS, 2)
gemm2(const __nv_bfloat16* __restrict__ A,      // [M][KA]
      const __nv_bfloat16* __restrict__ Bm,     // [B2?2K:K][N]
      const float* __restrict__ bias,
      const float* __restrict__ res,
      float* __restrict__ outF,
      __nv_bfloat16* __restrict__ outH,
      int N, int K, int KA, int nOff) {
    extern __shared__ char smem[];
    __nv_bfloat16* sm = (__nv_bfloat16*)smem;
    float*         Cs = (float*)smem;

    int tid  = threadIdx.x;
    int warp = tid >> 5;
    int wm   = warp >> 1;
    int wn   = warp & 1;
    int bn   = nOff + blockIdx.x * Bb_N;
    int bm   = blockIdx.y * Bb_M;
    int T    = K / Bb_K;

    wmma::fragment<wmma::accumulator, 16, 16, 16, float> acc[4][4];
    #pragma unroll
    for (int i = 0; i < 4; i++)
        #pragma unroll
        for (int j = 0; j < 4; j++)
            wmma::fill_fragment(acc[i][j], 0.0f);

    auto loads = [&](int t) {
        int k0 = t * Bb_K;
        int st = t % STAGES;
        __nv_bfloat16* AH = sm + st * STAGE_E;
        __nv_bfloat16* AL = AH + AH_ST;
        __nv_bfloat16* BH = AL + AH_ST;
        __nv_bfloat16* BL = BH + BH_ST;
        #pragma unroll
        for (int i = 0; i < 4; i++) {
            int c = tid + i * NTHREADS;
            int r = c >> 2, cc = (c & 3) * 8;
            const __nv_bfloat16* src = A + (size_t)(bm + r) * KA + k0 + cc;
            cpa16(&AH[r * LDA + cc], src);
            if (A2) cpa16(&AL[r * LDA + cc], src + K);
        }
        #pragma unroll
        for (int i = 0; i < 4; i++) {
            int c = tid + i * NTHREADS;
            int r = c >> 4, cc = (c & 15) * 8;
            cpa16(&BH[r * LDB + cc], Bm + (size_t)(k0 + r) * N + bn + cc);
            if (B2)
                cpa16(&BL[r * LDB + cc], Bm + (size_t)(K + k0 + r) * N + bn + cc);
        }
        asm volatile("cp.async.commit_group;\n" ::);
    };

    loads(0);
    loads(1);

    for (int t = 0; t < T; t++) {
        asm volatile("cp.async.wait_group 1;\n" ::);
        __syncthreads();
        if (t + 2 < T) loads(t + 2);

        int st = t % STAGES;
        const __nv_bfloat16* AH = sm + st * STAGE_E;
        const __nv_bfloat16* AL = AH + AH_ST;
        const __nv_bfloat16* BH = AL + AH_ST;
        const __nv_bfloat16* BL = BH + BH_ST;

        #pragma unroll
        for (int kk = 0; kk < Bb_K; kk += 16) {
            wmma::fragment<wmma::matrix_a, 16, 16, 16, __nv_bfloat16, wmma::row_major> ah[4], al[4];
            wmma::fragment<wmma::matrix_b, 16, 16, 16, __nv_bfloat16, wmma::row_major> bf[4];
            #pragma unroll
            for (int i = 0; i < 4; i++) {
                wmma::load_matrix_sync(ah[i], &AH[(wm * 64 + i * 16) * LDA + kk], LDA);
                if (A2)
                    wmma::load_matrix_sync(al[i], &AL[(wm * 64 + i * 16) * LDA + kk], LDA);
            }
            #pragma unroll
            for (int j = 0; j < 4; j++)
                wmma::load_matrix_sync(bf[j], &BH[kk * LDB + wn * 64 + j * 16], LDB);
            #pragma unroll
            for (int i = 0; i < 4; i++)
                #pragma unroll
                for (int j = 0; j < 4; j++) {
                    wmma::mma_sync(acc[i][j], ah[i], bf[j], acc[i][j]);
                    if (A2) wmma::mma_sync(acc[i][j], al[i], bf[j], acc[i][j]);
                }
            if (B2) {
                #pragma unroll
                for (int j = 0; j < 4; j++)
                    wmma::load_matrix_sync(bf[j], &BL[kk * LDB + wn * 64 + j * 16], LDB);
                #pragma unroll
                for (int i = 0; i < 4; i++)
                    #pragma unroll
                    for (int j = 0; j < 4; j++)
                        wmma::mma_sync(acc[i][j], ah[i], bf[j], acc[i][j]);
            }
        }
    }

    asm volatile("cp.async.wait_all;\n" ::);
    __syncthreads();

    #pragma unroll
    for (int i = 0; i < 4; i++)
        #pragma unroll
        for (int j = 0; j < 4; j++)
            wmma::store_matrix_sync(&Cs[(wm * 64 + i * 16) * LDC_S + wn * 64 + j * 16],
                                    acc[i][j], LDC_S, wmma::mem_row_major);
    __syncthreads();

    #pragma unroll 4
    for (int e = 0; e < 32; e++) {
        int idx = tid + e * NTHREADS;
        int r = idx >> 5;
        int c = (idx & 31) * 4;
        float4 v = *(float4*)&Cs[r * LDC_S + c];
        int gr = bm + r, gc = bn + c;
        float4 bv = *(const float4*)(bias + gc);
        if (EPI == EPI_QKV) {
            float4 o = {v.x + bv.x, v.y + bv.y, v.z + bv.z, v.w + bv.w};
            *(float4*)(outF + (size_t)gr * N + gc) = o;
        } else if (EPI == EPI_PROJ) {
            int tok = win_row_to_token(gr);
            size_t off = (size_t)tok * DIM + gc;
            float4 rv = *(const float4*)(res + off);
            float4 o = {v.x + bv.x + rv.x, v.y + bv.y + rv.y,
                        v.z + bv.z + rv.z, v.w + bv.w + rv.w};
            *(float4*)(outF + off) = o;
        } else if (EPI == EPI_FC1) {
            float tv[4] = {v.x + bv.x, v.y + bv.y, v.z + bv.z, v.w + bv.w};
            __nv_bfloat16 h[4];
            #pragma unroll
            for (int q = 0; q < 4; q++)
                h[q] = __float2bfloat16(0.5f * tv[q] * (1.0f + erff(tv[q] * 0.70710678118654752f)));
            *(uint2*)(outH + (size_t)gr * HID + gc) = *(uint2*)h;
        } else { // EPI_FC2
            size_t off = (size_t)gr * N + gc;
            float4 rv = *(const float4*)(res + off);
            float4 o = {v.x + bv.x + rv.x, v.y + bv.y + rv.y,
                        v.z + bv.z + rv.z, v.w + bv.w + rv.w};
            *(float4*)(outF + off) = o;
        }
    }
}

// ---------------- attention: tf32 wmma, one block per (window, head), 128 threads ----------------
static constexpr int AQ_LD = 36;
static constexpr int AS_LD = 64;
static constexpr int OFF_Q = 0;
static constexpr int OFF_K = OFF_Q + 64 * AQ_LD;     // 2304
static constexpr int OFF_V = OFF_K + 64 * AQ_LD;     // 4608
static constexpr int OFF_S = OFF_V + 64 * AQ_LD;     // 6912
static constexpr int OFF_B = OFF_S + 64 * AS_LD;     // 11008
static constexpr int OFF_T = OFF_B + 228;            // 11236
static constexpr int ATT_SMEM = (OFF_T + 64) * 4;    // 45200 B

template<class Frag>
__device__ __forceinline__ void to_tf32(Frag& f) {
    #pragma unroll
    for (int t = 0; t < f.num_elements; t++) f.x[t] = wmma::__float_to_tf32(f.x[t]);
}

__global__ void attn_kernel(const float* __restrict__ qkv,
                            const float* __restrict__ table,
                            __nv_bfloat16* __restrict__ out1) {
    extern __shared__ float sm[];
    float* sQ = sm + OFF_Q;
    float* sK = sm + OFF_K;
    float* sV = sm + OFF_V;
    float* sS = sm + OFF_S;
    float* sB = sm + OFF_B;
    int*   sTok = (int*)(sm + OFF_T);

    int widx = blockIdx.x, head = blockIdx.y;
    int tid = threadIdx.x, lane = tid & 31, w = tid >> 5;

    if (tid < 225) sB[tid] = table[tid * HEADS + head];
    if (tid < 64)  sTok[tid] = win_row_to_token(widx * 64 + tid);
    __syncthreads();

    #pragma unroll
    for (int i = 0; i < 4; i++) {
        int c = tid + i * 128;
        int r = c >> 3, cc = (c & 7) * 4;
        size_t base = (size_t)sTok[r] * (3 * DIM) + head * HD + cc;
        *(float4*)&sQ[r * AQ_LD + cc] = *(const float4*)&qkv[base];
        *(float4*)&sK[r * AQ_LD + cc] = *(const float4*)&qkv[base + DIM];
        *(float4*)&sV[r * AQ_LD + cc] = *(const float4*)&qkv[base + 2 * DIM];
    }
    __syncthreads();

    // S = Q @ K^T  (warp w -> rows [w*16, w*16+16))
    {
        wmma::fragment<wmma::accumulator, 16, 16, 8, float> acc[4];
        #pragma unroll
        for (int j = 0; j < 4; j++) wmma::fill_fragment(acc[j], 0.0f);
        #pragma unroll
        for (int kk = 0; kk < 32; kk += 8) {
            wmma::fragment<wmma::matrix_a, 16, 16, 8, wmma::precision::tf32, wmma::row_major> af;
            wmma::load_matrix_sync(af, &sQ[(w * 16) * AQ_LD + kk], AQ_LD);
            to_tf32(af);
            #pragma unroll
            for (int j = 0; j < 4; j++) {
                wmma::fragment<wmma::matrix_b, 16, 16, 8, wmma::precision::tf32, wmma::col_major> bf;
                wmma::load_matrix_sync(bf, &sK[(j * 16) * AQ_LD + kk], AQ_LD);
                to_tf32(bf);
                wmma::mma_sync(acc[j], af, bf, acc[j]);
            }
        }
        #pragma unroll
        for (int j = 0; j < 4; j++)
            wmma::store_matrix_sync(&sS[(w * 16) * AS_LD + j * 16], acc[j], AS_LD, wmma::mem_row_major);
    }

    // softmax in place (warp-local rows)
    #pragma unroll 2
    for (int rr = 0; rr < 16; rr++) {
        int r = w * 16 + rr;
        int yi = r >> 3, xi = r & 7;
        int c0 = lane, c1 = lane + 32;
        int i0 = (yi - (c0 >> 3) + 7) * 15 + (xi - (c0 & 7) + 7);
        int i1 = (yi - (c1 >> 3) + 7) * 15 + (xi - (c1 & 7) + 7);
        float v0 = sS[r * AS_LD + c0] * SCALE + sB[i0];
        float v1 = sS[r * AS_LD + c1] * SCALE + sB[i1];
        float m = fmaxf(v0, v1);
        #pragma unroll
        for (int o = 16; o; o >>= 1) m = fmaxf(m, __shfl_xor_sync(0xffffffffu, m, o));
        float e0 = __expf(v0 - m), e1 = __expf(v1 - m);
        float s = e0 + e1;
        #pragma unroll
        for (int o = 16; o; o >>= 1) s += __shfl_xor_sync(0xffffffffu, s, o);
        float inv = 1.0f / s;
        sS[r * AS_LD + c0] = e0 * inv;
        sS[r * AS_LD + c1] = e1 * inv;
    }
    __syncwarp();

    // O = P @ V (warp-local rows)
    {
        wmma::fragment<wmma::accumulator, 16, 16, 8, float> acc[2];
        #pragma unroll
        for (int j = 0; j < 2; j++) wmma::fill_fragment(acc[j], 0.0f);
        #pragma unroll
        for (int k0 = 0; k0 < 64; k0 += 8) {
            wmma::fragment<wmma::matrix_a, 16, 16, 8, wmma::precision::tf32, wmma::row_major> af;
            wmma::load_matrix_sync(af, &sS[(w * 16) * AS_LD + k0], AS_LD);
            to_tf32(af);
            #pragma unroll
            for (int j = 0; j < 2; j++) {
                wmma::fragment<wmma::matrix_b, 16, 16, 8, wmma::precision::tf32, wmma::row_major> bf;
                wmma::load_matrix_sync(bf, &sV[k0 * AQ_LD + j * 16], AQ_LD);
                to_tf32(bf);
                wmma::mma_sync(acc[j], af, bf, acc[j]);
            }
        }
        #pragma unroll
        for (int j = 0; j < 2; j++)
            wmma::store_matrix_sync(&sS[(w * 16) * AS_LD + j * 16], acc[j], AS_LD, wmma::mem_row_major);
    }
    __syncthreads();

    // write O (windowed order), single bf16 (proj is 1-term)
    #pragma unroll
    for (int i = 0; i < 16; i++) {
        int idx = tid + i * 128;
        int r = idx >> 5, c = idx & 31;
        out1[((size_t)widx * 64 + r) * DIM + head * HD + c] =
            __float2bfloat16(sS[r * AS_LD + c]);
    }
}

// ---------------- launch ----------------
extern "C" void kernel_launch(void* const* d_in, const int* in_sizes, int n_in,
                              void* d_out, int out_size) {
    const float* x        = (const float*)d_in[0];
    const float* norm1_g  = (const float*)d_in[1];
    const float* norm1_b  = (const float*)d_in[2];
    const float* qkv_w    = (const float*)d_in[3];
    const float* qkv_b    = (const float*)d_in[4];
    const float* bias_tab = (const float*)d_in[5];
    const float* proj_w   = (const float*)d_in[6];
    const float* proj_b   = (const float*)d_in[7];
    const float* norm2_g  = (const float*)d_in[8];
    const float* norm2_b  = (const float*)d_in[9];
    const float* fc1_w    = (const float*)d_in[10];
    const float* fc1_b    = (const float*)d_in[11];
    const float* fc2_w    = (const float*)d_in[12];
    const float* fc2_b    = (const float*)d_in[13];
    float* out            = (float*)d_out;

    void *p;
    cudaGetSymbolAddress(&p, g_h2);    __nv_bfloat16* ph2   = (__nv_bfloat16*)p;
    cudaGetSymbolAddress(&p, g_qkv);   float*         pqkv  = (float*)p;
    cudaGetSymbolAddress(&p, g_attn1); __nv_bfloat16* pat1  = (__nv_bfloat16*)p;
    cudaGetSymbolAddress(&p, g_x2);    float*         px2   = (float*)p;
    cudaGetSymbolAddress(&p, g_ln21);  __nv_bfloat16* pln21 = (__nv_bfloat16*)p;
    cudaGetSymbolAddress(&p, g_hid1);  __nv_bfloat16* phid1 = (__nv_bfloat16*)p;
    cudaGetSymbolAddress(&p, g_wqkv2); __nv_bfloat16* pwq2  = (__nv_bfloat16*)p;
    cudaGetSymbolAddress(&p, g_wproj1);__nv_bfloat16* pwp1  = (__nv_bfloat16*)p;
    cudaGetSymbolAddress(&p, g_wfc11); __nv_bfloat16* pw11  = (__nv_bfloat16*)p;
    cudaGetSymbolAddress(&p, g_wfc21); __nv_bfloat16* pw21  = (__nv_bfloat16*)p;

    cudaFuncSetAttribute((const void*)gemm2<EPI_QKV, 1, 1>,  cudaFuncAttributeMaxDynamicSharedMemorySize, SMEM_GEMM);
    cudaFuncSetAttribute((const void*)gemm2<EPI_QKV, 1, 0>,  cudaFuncAttributeMaxDynamicSharedMemorySize, SMEM_GEMM);
    cudaFuncSetAttribute((const void*)gemm2<EPI_PROJ, 0, 0>, cudaFuncAttributeMaxDynamicSharedMemorySize, SMEM_GEMM);
    cudaFuncSetAttribute((const void*)gemm2<EPI_FC1, 0, 0>,  cudaFuncAttributeMaxDynamicSharedMemorySize, SMEM_GEMM);
    cudaFuncSetAttribute((const void*)gemm2<EPI_FC2, 0, 0>,  cudaFuncAttributeMaxDynamicSharedMemorySize, SMEM_GEMM);
    cudaFuncSetAttribute(attn_kernel, cudaFuncAttributeMaxDynamicSharedMemorySize, ATT_SMEM);

    const int MT = MROWS / Bb_M;   // 1152

    // 0. weights
    cvt_all<<<(786432 + 255)/256, 256>>>(qkv_w, proj_w, fc1_w, fc2_w, pwq2, pwp1, pw11, pw21);

    // 1. LN1 -> h2 (2-component)
    ln_split_kernel<<<MROWS/8, 256>>>(x, norm1_g, norm1_b, ph2);

    // 2a. QKV q,k columns (N [0,512), 3-term) -> qkv f32
    gemm2<EPI_QKV, 1, 1><<<dim3(4, MT), NTHREADS, SMEM_GEMM>>>(
        ph2, pwq2, qkv_b, nullptr, pqkv, nullptr, 3*DIM, DIM, 2*DIM, 0);
    // 2b. QKV v columns (N [512,768), 2-term A-split)
    gemm2<EPI_QKV, 1, 0><<<dim3(2, MT), NTHREADS, SMEM_GEMM>>>(
        ph2, pwq2, qkv_b, nullptr, pqkv, nullptr, 3*DIM, DIM, 2*DIM, 512);

    // 3. windowed attention (tf32) -> attn1 (single bf16, windowed order)
    attn_kernel<<<dim3(NWIN, HEADS), 128, ATT_SMEM>>>(pqkv, bias_tab, pat1);

    // 4. proj (1-term) + shortcut scatter -> x2
    gemm2<EPI_PROJ, 0, 0><<<dim3(2, MT), NTHREADS, SMEM_GEMM>>>(
        pat1, pwp1, proj_b, x, px2, nullptr, DIM, DIM, DIM, 0);

    // 5. LN2 -> ln21 (single)
    ln_single_kernel<<<MROWS/8, 256>>>(px2, norm2_g, norm2_b, pln21);

    // 6. fc1 (1-term) + GELU -> hid1
    gemm2<EPI_FC1, 0, 0><<<dim3(8, MT), NTHREADS, SMEM_GEMM>>>(
        pln21, pw11, fc1_b, nullptr, nullptr, phid1, HID, DIM, DIM, 0);

    // 7. fc2 (1-term) + residual -> out
    gemm2<EPI_FC2, 0, 0><<<dim3(2, MT), NTHREADS, SMEM_GEMM>>>(
        phid1, pw21, fc2_b, px2, out, nullptr, DIM, HID, HID, 0);
}